// round 17
// baseline (speedup 1.0000x reference)
#include <cuda_runtime.h>
#include <math.h>
#include <float.h>

// RMSPELoss R14: warp-autonomous fused kernel. Each warp owns 4 rows
// (181 int4, 16B-aligned): 6 front-batched label LDG.128 + logits scalar
// (MLP=7), filter hits into per-warp smem slots, __syncwarp only, lanes 0-3
// finish the 4 rows in registers. No block barrier between load and consume.

#define BATCH 131072
#define NC 181
#define PI_F 3.14159265358979323846f
#define TWOPI_F 6.283185307179586f
#define INV_TWOPI_F 0.15915494309189535f

#define THREADS 256
#define WARPS (THREADS / 32)
#define ROWS_PER_WARP 4
#define ROWS_PER_BLOCK (WARPS * ROWS_PER_WARP)        // 32
#define NBLOCKS (BATCH / ROWS_PER_BLOCK)              // 4096
#define INT4_PER_WARP 181                             // 4 rows * 181 ints / 4

__device__ double   g_acc;    // zero-init; reset by last block each call
__device__ unsigned g_done;   // zero-init; reset by last block each call

__global__ __launch_bounds__(THREADS)
void rmspe_warp(const float* __restrict__ logits, const int* __restrict__ labels,
                float* __restrict__ out) {
    __shared__ int   s_cnt[WARPS][4];
    __shared__ int   s_idx[WARPS][4][4];
    __shared__ float s_part[WARPS];

    const int tid  = threadIdx.x;
    const int lane = tid & 31;
    const int w    = tid >> 5;
    const long rowg0 = (long)blockIdx.x * ROWS_PER_BLOCK + w * ROWS_PER_WARP;

    // ---- per-warp init + ONE latency wave (6 label int4 + logits scalar) ----
    if (lane < 4) s_cnt[w][lane] = 0;

    const int4* __restrict__ g4 = reinterpret_cast<const int4*>(labels)
                                + ((long)blockIdx.x * (ROWS_PER_BLOCK * NC / 4)
                                   + w * INT4_PER_WARP);
    int4 v[6];
    #pragma unroll
    for (int j = 0; j < 6; j++) {
        int i = lane + 32 * j;
        v[j] = make_int4(0, 0, 0, 0);
        if (i < INT4_PER_WARP) v[j] = __ldcs(&g4[i]);   // front-batched
    }
    float f = 0.0f;
    if (lane < 16)                                      // 4 rows x 4 scalars
        f = __ldg(&logits[(rowg0 + (lane >> 2)) * NC + (lane & 3)]);
    __syncwarp();                                       // s_cnt zero visible

    // ---- filter the warp's 724 ints into per-warp slots (smem ATOMS) ----
    #pragma unroll
    for (int j = 0; j < 6; j++) {
        int4 x = v[j];
        if ((x.x | x.y | x.z | x.w) != 0) {             // rare
            int linear = (lane + 32 * j) * 4;           // 0..723
            int vals[4] = {x.x, x.y, x.z, x.w};
            #pragma unroll
            for (int k = 0; k < 4; k++) {
                if (vals[k] == 1) {
                    int l = linear + k;
                    int r = l / NC;                     // local row 0..3
                    int c = l - r * NC;
                    int p = atomicAdd(&s_cnt[w][r], 1);
                    if (p < 4) s_idx[w][r][p] = c;
                }
            }
        }
    }
    __syncwarp();

    // ---- doa broadcast (convergent shuffles), lanes 0-3 finish 4 rows ----
    int rsel = lane & 3;
    float doa[4];
    #pragma unroll
    for (int k = 0; k < 4; k++)
        doa[k] = __shfl_sync(0xffffffffu, f, rsel * 4 + k);

    float rmse = 0.0f;
    if (lane < 4) {
        float ang[4];
        #pragma unroll
        for (int k = 0; k < 4; k++)
            ang[k] = ((float)s_idx[w][lane][k] - 90.0f) * (PI_F / 180.0f);

        float cost[4][4];
        #pragma unroll
        for (int i = 0; i < 4; i++) {
            #pragma unroll
            for (int j = 0; j < 4; j++) {
                float x = doa[i] - ang[j] + PI_F;
                float m = x - TWOPI_F * floorf(x * INV_TWOPI_F);  // mod [0,2pi)
                float d = m - PI_F;
                cost[i][j] = d * d;
            }
        }

        float best = FLT_MAX;
        #define P4(a,b,c,e) best = fminf(best, cost[0][a] + cost[1][b] + cost[2][c] + cost[3][e]);
        P4(0,1,2,3) P4(0,1,3,2) P4(0,2,1,3) P4(0,2,3,1) P4(0,3,1,2) P4(0,3,2,1)
        P4(1,0,2,3) P4(1,0,3,2) P4(1,2,0,3) P4(1,2,3,0) P4(1,3,0,2) P4(1,3,2,0)
        P4(2,0,1,3) P4(2,0,3,1) P4(2,1,0,3) P4(2,1,3,0) P4(2,3,0,1) P4(2,3,1,0)
        P4(3,0,1,2) P4(3,0,2,1) P4(3,1,0,2) P4(3,1,2,0) P4(3,2,0,1) P4(3,2,1,0)
        #undef P4

        rmse = sqrtf(best * 0.25f);
    }

    // sum the 4 row results (lanes >=4 contribute 0)
    #pragma unroll
    for (int off = 16; off; off >>= 1)
        rmse += __shfl_down_sync(0xffffffffu, rmse, off);
    if (lane == 0) s_part[w] = rmse;

    // ---- single trailing block barrier + 1 double RED + epilogue ----
    __syncthreads();
    if (tid == 0) {
        float x = 0.0f;
        #pragma unroll
        for (int i = 0; i < WARPS; i++) x += s_part[i];
        atomicAdd(&g_acc, (double)x);
        __threadfence();
        unsigned prev = atomicAdd(&g_done, 1u);
        if (prev == NBLOCKS - 1) {
            __threadfence();
            double total = *((volatile double*)&g_acc);
            out[0] = (float)(total / (double)BATCH);
            g_acc  = 0.0;    // deterministic state for next graph replay
            g_done = 0u;
        }
    }
}

extern "C" void kernel_launch(void* const* d_in, const int* in_sizes, int n_in,
                              void* d_out, int out_size) {
    const float* logits = (const float*)d_in[0];
    const int*   labels = (const int*)d_in[1];
    float* out = (float*)d_out;

    rmspe_warp<<<NBLOCKS, THREADS>>>(logits, labels, out);
}